// round 1
// baseline (speedup 1.0000x reference)
#include <cuda_runtime.h>
#include <math.h>

#define NN    50000
#define NPAD  50048          // 782 * 64
#define DD    128
#define EE    800000

// ---------------- scratch (device globals; no allocation) ----------------
__device__ float g_H[(size_t)NPAD * 512];    // [hx_on | hp_on | hx_tg | hp_tg] per row
__device__ float g_AGG[(size_t)NPAD * 512];  // aggregated, same layout
__device__ float g_P1[(size_t)NPAD * 256];   // [h1x | h1y]
__device__ int   g_deg[NN];
__device__ int   g_off[NN + 8];
__device__ int   g_cur[NN];
__device__ int   g_scol[EE];
__device__ float g_sw[EE];
__device__ float g_bnsum[512];               // [sum(256) | sumsq(256)]
__device__ float g_bnaff[512];               // [scale(256) | shift(256)]
__device__ float g_loss;

// ---------------- init ----------------
__global__ void k_zero() {
    int i = blockIdx.x * 256 + threadIdx.x;
    if (i < NN)  g_deg[i] = 0;
    if (i < 512) g_bnsum[i] = 0.f;
    if (i == 0)  g_loss = 0.f;
}

// ---------------- CSR build ----------------
__global__ void k_hist(const int* __restrict__ row) {
    int e = blockIdx.x * 256 + threadIdx.x;
    if (e < EE) atomicAdd(&g_deg[row[e]], 1);
}

__global__ void k_scan() {
    __shared__ int swarp[32];
    int t = threadIdx.x, lane = t & 31, wid = t >> 5;
    int running = 0;
    for (int base = 0; base < NN; base += 1024) {
        int idx = base + t;
        int v = (idx < NN) ? g_deg[idx] : 0;
        int incl = v;
        #pragma unroll
        for (int s = 1; s < 32; s <<= 1) {
            int a = __shfl_up_sync(0xFFFFFFFFu, incl, s);
            if (lane >= s) incl += a;
        }
        if (lane == 31) swarp[wid] = incl;
        __syncthreads();
        if (wid == 0) {
            int wv = swarp[lane];
            #pragma unroll
            for (int s = 1; s < 32; s <<= 1) {
                int a = __shfl_up_sync(0xFFFFFFFFu, wv, s);
                if (lane >= s) wv += a;
            }
            swarp[lane] = wv;
        }
        __syncthreads();
        int pre = (wid > 0) ? swarp[wid - 1] : 0;
        int excl = running + pre + incl - v;
        if (idx < NN) { g_off[idx] = excl; g_cur[idx] = excl; }
        running += swarp[31];
        __syncthreads();
    }
    if (t == 0) g_off[NN] = running;
}

__global__ void k_scatter(const int* __restrict__ row, const int* __restrict__ col,
                          const float* __restrict__ w) {
    int e = blockIdx.x * 256 + threadIdx.x;
    if (e < EE) {
        int r = row[e];
        int p = atomicAdd(&g_cur[r], 1);
        g_scol[p] = col[e];
        g_sw[p]   = w[e];
    }
}

// ---------------- shared GEMM core: 64x128 tile, 128 threads, 8x8 microtile ----------------
__device__ __forceinline__ void gemm_64x128(const float* As, const float* Bs,
                                            int tx, int ty, float acc[8][8]) {
    #pragma unroll
    for (int r = 0; r < 8; r++)
        #pragma unroll
        for (int j = 0; j < 8; j++) acc[r][j] = 0.f;
    const float* Ab = As + ty * 8 * DD;
    #pragma unroll 4
    for (int k = 0; k < DD; k++) {
        float4 b0 = *(const float4*)(Bs + k * DD + tx * 4);
        float4 b1 = *(const float4*)(Bs + k * DD + 64 + tx * 4);
        #pragma unroll
        for (int r = 0; r < 8; r++) {
            float a = Ab[r * DD + k];
            acc[r][0] += a * b0.x; acc[r][1] += a * b0.y;
            acc[r][2] += a * b0.z; acc[r][3] += a * b0.w;
            acc[r][4] += a * b1.x; acc[r][5] += a * b1.y;
            acc[r][6] += a * b1.z; acc[r][7] += a * b1.w;
        }
    }
}

// ---------------- feature GEMMs: H = {x,perb} @ {W_on,W_tg} ----------------
__global__ __launch_bounds__(128) void k_gemm_feat(const float* __restrict__ x,
                                                   const float* __restrict__ perb,
                                                   const float* __restrict__ W_on,
                                                   const float* __restrict__ W_tg) {
    extern __shared__ float sm[];
    float* As = sm;            // 64*128
    float* Bs = sm + 64 * DD;  // 128*128
    int t = threadIdx.x;
    int sec = blockIdx.y;      // 0: x@Won, 1: perb@Won, 2: x@Wtg, 3: perb@Wtg
    int row0 = blockIdx.x * 64;
    const float* A = (sec == 0 || sec == 2) ? x : perb;
    const float* W = (sec < 2) ? W_on : W_tg;

    const float4* W4 = (const float4*)W;
    float4* Bs4 = (float4*)Bs;
    #pragma unroll
    for (int i = 0; i < 32; i++) Bs4[t + i * 128] = W4[t + i * 128];

    float4* As4 = (float4*)As;
    #pragma unroll
    for (int i = 0; i < 16; i++) {
        int idx = t + i * 128;
        int r = idx >> 5, c = idx & 31;
        int gr = row0 + r;
        float4 v = make_float4(0.f, 0.f, 0.f, 0.f);
        if (gr < NN) v = ((const float4*)(A + (size_t)gr * DD))[c];
        As4[idx] = v;
    }
    __syncthreads();

    int tx = t & 15, ty = t >> 4;
    float acc[8][8];
    gemm_64x128(As, Bs, tx, ty, acc);

    #pragma unroll
    for (int r = 0; r < 8; r++) {
        int gr = row0 + ty * 8 + r;
        float* o = g_H + (size_t)gr * 512 + sec * 128;
        *(float4*)(o + tx * 4)      = make_float4(acc[r][0], acc[r][1], acc[r][2], acc[r][3]);
        *(float4*)(o + 64 + tx * 4) = make_float4(acc[r][4], acc[r][5], acc[r][6], acc[r][7]);
    }
}

// ---------------- sparse aggregation: AGG[r] = sum_e w_e * H[col_e] ----------------
__global__ __launch_bounds__(128) void k_aggregate() {
    int t = threadIdx.x;
    const float4* H4 = (const float4*)g_H;
    float4* A4 = (float4*)g_AGG;
    #pragma unroll
    for (int rr = 0; rr < 4; rr++) {
        int r = blockIdx.x * 4 + rr;
        int s = g_off[r], e = g_off[r + 1];
        float ax = 0.f, ay = 0.f, az = 0.f, aw = 0.f;
        int i = s;
        for (; i + 4 <= e; i += 4) {
            int c0 = g_scol[i], c1 = g_scol[i + 1], c2 = g_scol[i + 2], c3 = g_scol[i + 3];
            float w0 = g_sw[i], w1 = g_sw[i + 1], w2 = g_sw[i + 2], w3 = g_sw[i + 3];
            float4 h0 = H4[(size_t)c0 * 128 + t];
            float4 h1 = H4[(size_t)c1 * 128 + t];
            float4 h2 = H4[(size_t)c2 * 128 + t];
            float4 h3 = H4[(size_t)c3 * 128 + t];
            ax += w0 * h0.x + w1 * h1.x + w2 * h2.x + w3 * h3.x;
            ay += w0 * h0.y + w1 * h1.y + w2 * h2.y + w3 * h3.y;
            az += w0 * h0.z + w1 * h1.z + w2 * h2.z + w3 * h3.z;
            aw += w0 * h0.w + w1 * h1.w + w2 * h2.w + w3 * h3.w;
        }
        for (; i < e; i++) {
            int c = g_scol[i]; float w = g_sw[i];
            float4 h = H4[(size_t)c * 128 + t];
            ax += w * h.x; ay += w * h.y; az += w * h.z; aw += w * h.w;
        }
        A4[(size_t)r * 128 + t] = make_float4(ax, ay, az, aw);
    }
}

// ---------------- embed = x + perb + agg_on_x + agg_on_p + b_on ----------------
__global__ void k_embed(const float* __restrict__ x, const float* __restrict__ perb,
                        const float* __restrict__ b_on, float* __restrict__ out) {
    int id = blockIdx.x * 256 + threadIdx.x;  // float4 index
    if (id < NN * 32) {
        int r = id >> 5, c = id & 31;
        float4 xv = ((const float4*)x)[id];
        float4 pv = ((const float4*)perb)[id];
        float4 a0 = ((const float4*)g_AGG)[(size_t)r * 128 + c];
        float4 a1 = ((const float4*)g_AGG)[(size_t)r * 128 + 32 + c];
        float4 bv = ((const float4*)b_on)[c];
        ((float4*)out)[id] = make_float4(xv.x + pv.x + a0.x + a1.x + bv.x,
                                         xv.y + pv.y + a0.y + a1.y + bv.y,
                                         xv.z + pv.z + a0.z + a1.z + bv.z,
                                         xv.w + pv.w + a0.w + a1.w + bv.w);
    }
}

// ---------------- predictor stage 1: P1 = (online_{x,y}) @ W1 + b1 ----------------
__global__ __launch_bounds__(128) void k_pred1(const float* __restrict__ b_on,
                                               const float* __restrict__ W1,
                                               const float* __restrict__ b1) {
    extern __shared__ float sm[];
    float* As = sm;
    float* Bs = sm + 64 * DD;
    int t = threadIdx.x;
    int v = blockIdx.y;               // 0: online_x, 1: online_y
    int row0 = blockIdx.x * 64;

    const float4* W4 = (const float4*)W1;
    float4* Bs4 = (float4*)Bs;
    #pragma unroll
    for (int i = 0; i < 32; i++) Bs4[t + i * 128] = W4[t + i * 128];

    const float4* AG4 = (const float4*)g_AGG;
    const float4* bon4 = (const float4*)b_on;
    float4* As4 = (float4*)As;
    #pragma unroll
    for (int i = 0; i < 16; i++) {
        int idx = t + i * 128;
        int r = idx >> 5, c = idx & 31;
        int gr = row0 + r;
        float4 a = AG4[(size_t)gr * 128 + c];
        if (v) {
            float4 u = AG4[(size_t)gr * 128 + 32 + c];
            a.x += u.x; a.y += u.y; a.z += u.z; a.w += u.w;
        }
        float4 b = bon4[c];
        a.x += b.x; a.y += b.y; a.z += b.z; a.w += b.w;
        As4[idx] = a;
    }
    __syncthreads();

    int tx = t & 15, ty = t >> 4;
    float acc[8][8];
    gemm_64x128(As, Bs, tx, ty, acc);

    float4 bb0 = ((const float4*)b1)[tx];
    float4 bb1 = ((const float4*)b1)[16 + tx];
    #pragma unroll
    for (int r = 0; r < 8; r++) {
        int gr = row0 + ty * 8 + r;
        float* o = g_P1 + (size_t)gr * 256 + v * 128;
        *(float4*)(o + tx * 4)      = make_float4(acc[r][0] + bb0.x, acc[r][1] + bb0.y,
                                                  acc[r][2] + bb0.z, acc[r][3] + bb0.w);
        *(float4*)(o + 64 + tx * 4) = make_float4(acc[r][4] + bb1.x, acc[r][5] + bb1.y,
                                                  acc[r][6] + bb1.z, acc[r][7] + bb1.w);
    }
}

// ---------------- BN stats ----------------
__global__ void k_bn_stats() {
    int t = threadIdx.x;  // column 0..255
    int r0 = blockIdx.x * 256;
    float s = 0.f, q = 0.f;
    for (int rr = 0; rr < 256; rr++) {
        int r = r0 + rr;
        if (r < NN) {
            float xv = g_P1[(size_t)r * 256 + t];
            s += xv; q += xv * xv;
        }
    }
    atomicAdd(&g_bnsum[t], s);
    atomicAdd(&g_bnsum[256 + t], q);
}

__global__ void k_bn_final(const float* __restrict__ bn_g, const float* __restrict__ bn_b) {
    int t = threadIdx.x;  // 0..255
    float inv_n = 1.f / (float)NN;
    float mean = g_bnsum[t] * inv_n;
    float var = g_bnsum[256 + t] * inv_n - mean * mean;
    int f = t & 127;
    float sc = bn_g[f] * rsqrtf(var + 1e-5f);
    g_bnaff[t] = sc;
    g_bnaff[256 + t] = bn_b[f] - mean * sc;
}

// ---------------- predictor stage 2 + cosine loss ----------------
__global__ __launch_bounds__(128) void k_pred2_loss(const float* __restrict__ b_tg,
                                                    const float* __restrict__ prelu_a,
                                                    const float* __restrict__ W2,
                                                    const float* __restrict__ b2) {
    extern __shared__ float sm[];
    float* As = sm;
    float* Bs = sm + 64 * DD;
    __shared__ float ssc[128], ssh[128], warp_l[4];
    int t = threadIdx.x;
    int v = blockIdx.y;               // 0: px vs target_x, 1: py vs target_y
    int row0 = blockIdx.x * 64;

    ssc[t] = g_bnaff[v * 128 + t];
    ssh[t] = g_bnaff[256 + v * 128 + t];
    const float4* W4 = (const float4*)W2;
    float4* Bs4 = (float4*)Bs;
    #pragma unroll
    for (int i = 0; i < 32; i++) Bs4[t + i * 128] = W4[t + i * 128];
    float alpha = prelu_a[0];
    __syncthreads();

    float4* As4 = (float4*)As;
    #pragma unroll
    for (int i = 0; i < 16; i++) {
        int idx = t + i * 128;
        int r = idx >> 5, c4 = idx & 31;
        int gr = row0 + r;
        float4 p = *(const float4*)(g_P1 + (size_t)gr * 256 + v * 128 + c4 * 4);
        int c = c4 * 4;
        float v0 = p.x * ssc[c] + ssh[c];         v0 = v0 > 0.f ? v0 : alpha * v0;
        float v1 = p.y * ssc[c + 1] + ssh[c + 1]; v1 = v1 > 0.f ? v1 : alpha * v1;
        float v2 = p.z * ssc[c + 2] + ssh[c + 2]; v2 = v2 > 0.f ? v2 : alpha * v2;
        float v3 = p.w * ssc[c + 3] + ssh[c + 3]; v3 = v3 > 0.f ? v3 : alpha * v3;
        As4[idx] = make_float4(v0, v1, v2, v3);
    }
    __syncthreads();

    int tx = t & 15, ty = t >> 4;
    float acc[8][8];
    gemm_64x128(As, Bs, tx, ty, acc);
    __syncthreads();   // everyone done reading As before we reuse it for px

    float4 bb0 = ((const float4*)b2)[tx];
    float4 bb1 = ((const float4*)b2)[16 + tx];
    #pragma unroll
    for (int r = 0; r < 8; r++) {
        int lr = ty * 8 + r;
        *(float4*)(As + lr * 128 + tx * 4) =
            make_float4(acc[r][0] + bb0.x, acc[r][1] + bb0.y, acc[r][2] + bb0.z, acc[r][3] + bb0.w);
        *(float4*)(As + lr * 128 + 64 + tx * 4) =
            make_float4(acc[r][4] + bb1.x, acc[r][5] + bb1.y, acc[r][6] + bb1.z, acc[r][7] + bb1.w);
    }
    __syncthreads();

    int lane = t & 31, w = t >> 5;
    const float4* btg4 = (const float4*)b_tg;
    float lsum = 0.f;
    for (int rr = 0; rr < 16; rr++) {
        int r = w * 16 + rr;
        int gr = row0 + r;
        if (gr < NN) {
            float4 px = *(const float4*)(As + r * 128 + lane * 4);
            float4 tg = *(const float4*)(g_AGG + (size_t)gr * 512 + 256 + lane * 4);
            if (v == 0) {  // target_x = agg_tg_x + agg_tg_p + b_tg
                float4 u = *(const float4*)(g_AGG + (size_t)gr * 512 + 384 + lane * 4);
                tg.x += u.x; tg.y += u.y; tg.z += u.z; tg.w += u.w;
            }
            float4 bt = btg4[lane];
            tg.x += bt.x; tg.y += bt.y; tg.z += bt.z; tg.w += bt.w;
            float dot = px.x * tg.x + px.y * tg.y + px.z * tg.z + px.w * tg.w;
            float np  = px.x * px.x + px.y * px.y + px.z * px.z + px.w * px.w;
            float nt  = tg.x * tg.x + tg.y * tg.y + tg.z * tg.z + tg.w * tg.w;
            #pragma unroll
            for (int s = 16; s; s >>= 1) {
                dot += __shfl_xor_sync(0xFFFFFFFFu, dot, s);
                np  += __shfl_xor_sync(0xFFFFFFFFu, np, s);
                nt  += __shfl_xor_sync(0xFFFFFFFFu, nt, s);
            }
            if (lane == 0) {
                float d1 = fmaxf(sqrtf(np), 1e-12f);
                float d2 = fmaxf(sqrtf(nt), 1e-12f);
                lsum += 2.f - 2.f * dot / (d1 * d2);
            }
        }
    }
    if (lane == 0) warp_l[w] = lsum;
    __syncthreads();
    if (t == 0) atomicAdd(&g_loss, warp_l[0] + warp_l[1] + warp_l[2] + warp_l[3]);
}

__global__ void k_final(float* out, int out_size) {
    out[out_size - 1] = g_loss * (1.f / (float)NN);
}

// ---------------- host ----------------
extern "C" void kernel_launch(void* const* d_in, const int* in_sizes, int n_in,
                              void* d_out, int out_size) {
    const float* x       = (const float*)d_in[0];
    const float* perb    = (const float*)d_in[1];
    const int*   erow    = (const int*)d_in[2];
    const int*   ecol    = (const int*)d_in[3];
    const float* ew      = (const float*)d_in[4];
    const float* W_on    = (const float*)d_in[5];
    const float* b_on    = (const float*)d_in[6];
    const float* W_tg    = (const float*)d_in[7];
    const float* b_tg    = (const float*)d_in[8];
    const float* W1      = (const float*)d_in[9];
    const float* b1      = (const float*)d_in[10];
    const float* bn_g    = (const float*)d_in[11];
    const float* bn_b    = (const float*)d_in[12];
    const float* prelu_a = (const float*)d_in[13];
    const float* W2      = (const float*)d_in[14];
    const float* b2      = (const float*)d_in[15];
    float* out = (float*)d_out;

    const int SMEM = (64 * 128 + 128 * 128) * 4;  // 96 KB
    cudaFuncSetAttribute(k_gemm_feat, cudaFuncAttributeMaxDynamicSharedMemorySize, SMEM);
    cudaFuncSetAttribute(k_pred1, cudaFuncAttributeMaxDynamicSharedMemorySize, SMEM);
    cudaFuncSetAttribute(k_pred2_loss, cudaFuncAttributeMaxDynamicSharedMemorySize, SMEM);

    k_zero<<<196, 256>>>();
    k_hist<<<3125, 256>>>(erow);
    k_scan<<<1, 1024>>>();
    k_scatter<<<3125, 256>>>(erow, ecol, ew);
    k_gemm_feat<<<dim3(782, 4), 128, SMEM>>>(x, perb, W_on, W_tg);
    k_aggregate<<<12500, 128>>>();
    k_embed<<<6250, 256>>>(x, perb, b_on, out);
    k_pred1<<<dim3(782, 2), 128, SMEM>>>(b_on, W1, b1);
    k_bn_stats<<<196, 256>>>();
    k_bn_final<<<1, 256>>>(bn_g, bn_b);
    k_pred2_loss<<<dim3(782, 2), 128, SMEM>>>(b_tg, prelu_a, W2, b2);
    k_final<<<1, 1>>>(out, out_size);
}